// round 1
// baseline (speedup 1.0000x reference)
#include <cuda_runtime.h>
#include <cstdint>

// Problem constants (fixed shapes for this problem instance)
#define BB 32
#define HH 384
#define WW 1280
#define NP (HH*WW)            // 491520 points per batch
#define SS 256
#define GG (SS*SS)            // 65536 cells
#define NB 65536              // histogram bins
#define CAP 4096              // candidate buffer per batch
#define TOTAL_PTS (BB*NP)     // 15,728,640
#define TOTAL_CELLS (BB*GG)   // 2,097,152

#define YMINF (-16.0f)
#define BIN_SCALE (65536.0f/288.0f)

// ---------------- device scratch (static; no allocation) ----------------
__device__ unsigned long long g_packed[TOTAL_CELLS]; // occp|normp|occn|normn 16b each
__device__ unsigned int       g_ground[TOTAL_CELLS];
__device__ unsigned int       g_hist[BB*NB];
__device__ float              g_pos[TOTAL_CELLS];
__device__ float              g_neg[TOTAL_CELLS];
__device__ float              g_cand[BB*CAP];
__device__ int                g_candcnt[BB];
__device__ float              g_thr[BB];
__device__ int                g_sel[BB*3];   // binlo, binhi, cnt_before
__device__ int                g_is_int32;    // ground_mask dtype flag

__device__ __forceinline__ int y_to_bin(float y) {
    // force identical arithmetic in hist + cand kernels (no fma contraction)
    int bin = (int)__fmul_rn(__fsub_rn(y, YMINF), BIN_SCALE);
    return min(max(bin, 0), NB-1);
}

// ---------------- kernels ----------------
__global__ void zero_kernel() {
    int i = blockIdx.x*blockDim.x + threadIdx.x;
    if (i < TOTAL_CELLS) { g_packed[i] = 0ull; g_ground[i] = 0u; g_hist[i] = 0u; }
    if (i < BB) g_candcnt[i] = 0;
    if (i == 0) g_is_int32 = 1;
}

// detect ground_mask dtype: random 0/1 bytes read as int32 are almost never in {0,1}
__global__ void detect_kernel(const unsigned char* __restrict__ gm) {
    int i = blockIdx.x*blockDim.x + threadIdx.x;   // 8192 words checked
    const int* gi = (const int*)gm;
    int v = gi[i];
    if (v != 0 && v != 1) g_is_int32 = 0;
}

__global__ void __launch_bounds__(256) hist_kernel(const float* __restrict__ ptc) {
    int i = blockIdx.x*blockDim.x + threadIdx.x;
    if (i >= TOTAL_PTS) return;
    int b = i / NP; int n = i - b*NP;
    float y = ptc[(size_t)b*(3*NP) + NP + n];
    atomicAdd(&g_hist[b*NB + y_to_bin(y)], 1u);
}

__global__ void scan_kernel() {
    int b = blockIdx.x, t = threadIdx.x;
    const unsigned int* h = &g_hist[(size_t)b*NB];
    __shared__ unsigned int chunk[256];
    int base = t*256;
    unsigned int s = 0;
    #pragma unroll 4
    for (int i = 0; i < 256; i++) s += h[base+i];
    chunk[t] = s;
    __syncthreads();
    if (t == 0) {
        unsigned int run = 0;
        for (int i = 0; i < 256; i++) { unsigned int c = chunk[i]; chunk[i] = run; run += c; }
    }
    __syncthreads();
    float idxf = __fmul_rn(0.7f, (float)(NP-1));   // matches jax f32 index math
    unsigned int k = (unsigned int)floorf(idxf);
    unsigned int cum = chunk[t];
    for (int i = 0; i < 256; i++) {
        unsigned int c = h[base+i];
        if (k   >= cum && k   < cum + c) { g_sel[b*3+0] = base+i; g_sel[b*3+2] = (int)cum; }
        if (k+1 >= cum && k+1 < cum + c) { g_sel[b*3+1] = base+i; }
        cum += c;
    }
}

__global__ void __launch_bounds__(256) cand_kernel(const float* __restrict__ ptc) {
    int i = blockIdx.x*blockDim.x + threadIdx.x;
    if (i >= TOTAL_PTS) return;
    int b = i / NP; int n = i - b*NP;
    float y = ptc[(size_t)b*(3*NP) + NP + n];
    int bin = y_to_bin(y);
    int lo = g_sel[b*3+0], hi = g_sel[b*3+1];
    if (bin >= lo && bin <= hi) {
        int pos = atomicAdd(&g_candcnt[b], 1);
        if (pos < CAP) g_cand[b*CAP + pos] = y;
    }
}

__global__ void thr_kernel() {
    int b = blockIdx.x, t = threadIdx.x;
    int n = g_candcnt[b]; if (n > CAP) n = CAP;
    int cb = g_sel[b*3+2];
    float idxf = __fmul_rn(0.7f, (float)(NP-1));
    float lowf = floorf(idxf);
    float hw = __fsub_rn(idxf, lowf);     // high weight
    float lw = __fsub_rn(1.0f, hw);       // low weight
    int rk = (int)lowf - cb;              // rank of s[k] within candidates
    __shared__ float sk, sk1;
    if (t == 0) { sk = 0.f; sk1 = 0.f; }
    __syncthreads();
    for (int c = t; c < n; c += blockDim.x) {
        float v = g_cand[b*CAP + c];
        int r = 0;
        for (int j = 0; j < n; j++) {
            float u = g_cand[b*CAP + j];
            r += (u < v) || (u == v && j < c);
        }
        if (r == rk)     sk  = v;
        if (r == rk + 1) sk1 = v;
    }
    __syncthreads();
    if (t == 0)
        g_thr[b] = __fadd_rn(__fmul_rn(sk, lw), __fmul_rn(sk1, hw));
}

__global__ void __launch_bounds__(256) scatter_kernel(
    const float* __restrict__ ptc,
    const float* __restrict__ depth,
    const unsigned char* __restrict__ gm)
{
    int i = blockIdx.x*blockDim.x + threadIdx.x;
    if (i >= TOTAL_PTS) return;
    int b = i / NP; int n = i - b*NP;
    const float* p = ptc + (size_t)b*(3*NP);
    float x = p[n];
    float z = p[n + 2*NP];
    if (!(x >= 0.0f && x <= (float)(SS-1) && z >= 0.0f && z <= (float)(SS-1))) return;
    float y = p[n + NP];
    if (!(y < g_thr[b])) return;

    int xi = min(max((int)x, 0), SS-1);
    int zi = min(max((int)z, 0), SS-1);
    int cell = b*GG + zi*SS + xi;

    bool g;
    if (g_is_int32) g = (((const int*)gm)[i] != 0);
    else            g = (gm[i] != 0);

    if (g) { atomicAdd(&g_ground[cell], 1u); return; }

    // on-the-fly grad_pos / grad_neg from depth row stencil
    int r = n / WW; int j = n - r*WW;
    const float* drow = depth + (size_t)b*NP + (size_t)r*WW;
    int c1 = max(j-2, 0), c2 = min(j+2, WW-1);
    float diff1 = drow[min(c1+1, WW-1)] - drow[max(c1-1, 0)];
    float diff2 = drow[min(c2+1, WW-1)] - drow[max(c2-1, 0)];
    float rml1 = fmaxf(diff1, 0.f), rml2 = fmaxf(diff2, 0.f);
    float lmr1 = fmaxf(-diff1, 0.f), lmr2 = fmaxf(-diff2, 0.f);
    float rmldd = fmaxf(rml1 - rml2, 0.f);   // relu(-(d2 over dx)) right-minus-left
    float lmrdd = fmaxf(lmr2 - lmr1, 0.f);
    float gp = (j < WW/2) ? rmldd : lmrdd;
    float gn = (j < WW/2) ? lmrdd : rmldd;

    unsigned long long inc = 0ull;
    if (gp > 0.f) inc += (1ull << 32) + ((gp > 0.01f) ? (1ull << 48) : 0ull);
    if (gn > 0.f) inc += 1ull        + ((gn > 0.01f) ? (1ull << 16) : 0ull);
    if (inc) atomicAdd(&g_packed[cell], inc);
}

__global__ void __launch_bounds__(256) odds_kernel() {
    int i = blockIdx.x*blockDim.x + threadIdx.x;
    if (i >= TOTAL_CELLS) return;
    unsigned long long v = g_packed[i];
    unsigned int gc = g_ground[i];
    int occp = (int)(v >> 48);
    int np_  = (int)((v >> 32) & 0xFFFFull);
    int occn = (int)((v >> 16) & 0xFFFFull);
    int nn_  = (int)(v & 0xFFFFull);

    float PMIN = logf(0.1f) - log1pf(-0.1f);
    float PMAX = logf(0.9f) - log1pf(-0.9f);

    bool freep = (gc > 0) && (np_ == 0);
    bool unkp  = (!freep) && (np_ < 3);
    float po;
    if (freep)      po = logf(1e-10f) - log1pf(-1e-10f);
    else if (unkp)  po = 0.f;
    else { float pr = (float)occp / (float)np_; po = logf(pr) - log1pf(-pr); }
    po = fminf(fmaxf(po, PMIN), PMAX);

    bool freen = (gc > 0) && (nn_ == 0);
    bool unkn  = (!freen) && (nn_ < 3);
    float no;
    if (freen || unkn) no = logf(0.5f) - log1pf(-0.5f);
    else { float pr = (float)occn / (float)nn_; no = logf(pr) - log1pf(-pr); }
    if (freep || unkp) no = 0.f;
    no = fminf(fmaxf(no, 0.f), PMAX);

    g_pos[i] = po;
    g_neg[i] = no;
}

__global__ void __launch_bounds__(256) pool_kernel(float* __restrict__ out) {
    int i = blockIdx.x*blockDim.x + threadIdx.x;
    if (i >= TOTAL_CELLS) return;
    int b = i / GG; int c = i - b*GG;
    int zi = c / SS; int xi = c - zi*SS;
    const float* ng = &g_neg[(size_t)b*GG];
    float m = -3.4e38f;
    #pragma unroll
    for (int dz = -1; dz <= 1; dz++) {
        int zz = zi + dz;
        if (zz < 0 || zz >= SS) continue;
        #pragma unroll
        for (int dx = -1; dx <= 1; dx++) {
            int xx = xi + dx;
            if (xx < 0 || xx >= SS) continue;
            m = fmaxf(m, ng[zz*SS + xx]);
        }
    }
    out[i] = g_pos[i] - m;
}

// ---------------- launcher ----------------
extern "C" void kernel_launch(void* const* d_in, const int* in_sizes, int n_in,
                              void* d_out, int out_size) {
    const float*         depth = (const float*)d_in[0];
    const float*         ptc   = (const float*)d_in[1];
    const unsigned char* gm    = (const unsigned char*)d_in[2];
    float*               out   = (float*)d_out;

    const int TPB = 256;
    const int PT_BLKS   = (TOTAL_PTS   + TPB - 1) / TPB;   // 61440
    const int CELL_BLKS = (TOTAL_CELLS + TPB - 1) / TPB;   // 8192

    zero_kernel<<<CELL_BLKS, TPB>>>();
    detect_kernel<<<32, TPB>>>(gm);
    hist_kernel<<<PT_BLKS, TPB>>>(ptc);
    scan_kernel<<<BB, 256>>>();
    cand_kernel<<<PT_BLKS, TPB>>>(ptc);
    thr_kernel<<<BB, 256>>>();
    scatter_kernel<<<PT_BLKS, TPB>>>(ptc, depth, gm);
    odds_kernel<<<CELL_BLKS, TPB>>>();
    pool_kernel<<<CELL_BLKS, TPB>>>(out);
}

// round 2
// speedup vs baseline: 1.7931x; 1.7931x over previous
#include <cuda_runtime.h>
#include <cstdint>

// Problem constants (fixed shapes for this problem instance)
#define BB 32
#define HH 384
#define WW 1280
#define NP (HH*WW)            // 491520 points per batch
#define SS 256
#define GG (SS*SS)            // 65536 cells
#define NB 4096               // histogram bins
#define CAP 8192              // candidate buffer per batch
#define TOTAL_PTS (BB*NP)     // 15,728,640
#define TOTAL_CELLS (BB*GG)   // 2,097,152

#define YMINF (-16.0f)
#define BIN_SCALE (4096.0f/288.0f)

#define PTS_PER_HBLK 32768
#define HBLKS_PER_B (NP/PTS_PER_HBLK)   // 15

// ---------------- device scratch (static; no allocation) ----------------
// packed per-cell counters, 12-bit fields:
//   bits [48:60) occp | [36:48) normp | [24:36) occn | [12:24) normn | [0:12) ground
__device__ unsigned long long g_packed[TOTAL_CELLS];
__device__ unsigned int       g_hist[BB*NB];
__device__ float              g_cand[BB*CAP];
__device__ int                g_candcnt[BB];
__device__ float              g_thr[BB];
__device__ int                g_sel[BB*3];   // binlo, binhi, cnt_before
__device__ int                g_is_int32;    // ground_mask dtype flag

__device__ __forceinline__ int y_to_bin(float y) {
    // identical arithmetic in hist + cand kernels (no fma contraction)
    int bin = (int)__fmul_rn(__fsub_rn(y, YMINF), BIN_SCALE);
    return min(max(bin, 0), NB-1);
}

// ---------------- kernels ----------------
__global__ void zero_kernel() {
    int i = blockIdx.x*blockDim.x + threadIdx.x;
    if (i < TOTAL_CELLS) g_packed[i] = 0ull;
    if (i < BB*NB) g_hist[i] = 0u;
    if (i < BB) g_candcnt[i] = 0;
    if (i == 0) g_is_int32 = 1;
}

// detect ground_mask dtype: random 0/1 bytes read as int32 are almost never in {0,1}
__global__ void detect_kernel(const unsigned char* __restrict__ gm) {
    int i = blockIdx.x*blockDim.x + threadIdx.x;   // 8192 words checked
    const int* gi = (const int*)gm;
    int v = gi[i];
    if (v != 0 && v != 1) g_is_int32 = 0;
}

// privatized shared-memory histogram; one block = 32768 y's of one batch
__global__ void __launch_bounds__(256) hist_kernel(const float* __restrict__ ptc) {
    __shared__ unsigned int sh[NB];
    int b   = blockIdx.x / HBLKS_PER_B;
    int blk = blockIdx.x % HBLKS_PER_B;
    for (int i = threadIdx.x; i < NB; i += 256) sh[i] = 0u;
    __syncthreads();
    const float4* yp = (const float4*)(ptc + (size_t)b*(3*NP) + NP
                                       + (size_t)blk*PTS_PER_HBLK);
    #pragma unroll 4
    for (int i = threadIdx.x; i < PTS_PER_HBLK/4; i += 256) {
        float4 v = yp[i];
        atomicAdd(&sh[y_to_bin(v.x)], 1u);
        atomicAdd(&sh[y_to_bin(v.y)], 1u);
        atomicAdd(&sh[y_to_bin(v.z)], 1u);
        atomicAdd(&sh[y_to_bin(v.w)], 1u);
    }
    __syncthreads();
    unsigned int* gh = &g_hist[(size_t)b*NB];
    for (int i = threadIdx.x; i < NB; i += 256) {
        unsigned int s = sh[i];
        if (s) atomicAdd(&gh[i], s);
    }
}

__global__ void scan_kernel() {
    int b = blockIdx.x, t = threadIdx.x;
    const unsigned int* h = &g_hist[(size_t)b*NB];
    __shared__ unsigned int chunk[256];
    const int PER = NB/256;          // 16
    int base = t*PER;
    unsigned int s = 0;
    #pragma unroll
    for (int i = 0; i < PER; i++) s += h[base+i];
    chunk[t] = s;
    __syncthreads();
    if (t == 0) {
        unsigned int run = 0;
        for (int i = 0; i < 256; i++) { unsigned int c = chunk[i]; chunk[i] = run; run += c; }
    }
    __syncthreads();
    float idxf = __fmul_rn(0.7f, (float)(NP-1));   // matches jax f32 index math
    unsigned int k = (unsigned int)floorf(idxf);
    unsigned int cum = chunk[t];
    for (int i = 0; i < PER; i++) {
        unsigned int c = h[base+i];
        if (k   >= cum && k   < cum + c) { g_sel[b*3+0] = base+i; g_sel[b*3+2] = (int)cum; }
        if (k+1 >= cum && k+1 < cum + c) { g_sel[b*3+1] = base+i; }
        cum += c;
    }
}

__global__ void __launch_bounds__(256) cand_kernel(const float* __restrict__ ptc) {
    int i = blockIdx.x*blockDim.x + threadIdx.x;        // over TOTAL_PTS/4
    int b = i / (NP/4); int n4 = i - b*(NP/4);
    const float4* yp = (const float4*)(ptc + (size_t)b*(3*NP) + NP);
    float4 v = yp[n4];
    int lo = g_sel[b*3+0], hi = g_sel[b*3+1];
    float ys[4] = {v.x, v.y, v.z, v.w};
    #pragma unroll
    for (int q = 0; q < 4; q++) {
        int bin = y_to_bin(ys[q]);
        if (bin >= lo && bin <= hi) {
            int pos = atomicAdd(&g_candcnt[b], 1);
            if (pos < CAP) g_cand[b*CAP + pos] = ys[q];
        }
    }
}

__global__ void thr_kernel() {
    int b = blockIdx.x, t = threadIdx.x;
    int n = g_candcnt[b]; if (n > CAP) n = CAP;
    int cb = g_sel[b*3+2];
    float idxf = __fmul_rn(0.7f, (float)(NP-1));
    float lowf = floorf(idxf);
    float hw = __fsub_rn(idxf, lowf);     // high weight
    float lw = __fsub_rn(1.0f, hw);       // low weight
    int rk = (int)lowf - cb;              // rank of s[k] within candidates
    __shared__ float sk, sk1;
    if (t == 0) { sk = 0.f; sk1 = 0.f; }
    __syncthreads();
    for (int c = t; c < n; c += blockDim.x) {
        float v = g_cand[b*CAP + c];
        int r = 0;
        for (int j = 0; j < n; j++) {
            float u = g_cand[b*CAP + j];
            r += (u < v) || (u == v && j < c);
        }
        if (r == rk)     sk  = v;
        if (r == rk + 1) sk1 = v;
    }
    __syncthreads();
    if (t == 0)
        g_thr[b] = __fadd_rn(__fmul_rn(sk, lw), __fmul_rn(sk1, hw));
}

__global__ void __launch_bounds__(256) scatter_kernel(
    const float* __restrict__ ptc,
    const float* __restrict__ depth,
    const unsigned char* __restrict__ gm)
{
    int i = blockIdx.x*blockDim.x + threadIdx.x;
    if (i >= TOTAL_PTS) return;
    int b = i / NP; int n = i - b*NP;
    const float* p = ptc + (size_t)b*(3*NP);
    float x = p[n];
    float z = p[n + 2*NP];
    if (!(x >= 0.0f && x <= (float)(SS-1) && z >= 0.0f && z <= (float)(SS-1))) return;
    float y = p[n + NP];
    if (!(y < g_thr[b])) return;

    int xi = min(max((int)x, 0), SS-1);
    int zi = min(max((int)z, 0), SS-1);
    int cell = b*GG + zi*SS + xi;

    bool g;
    if (g_is_int32) g = (((const int*)gm)[i] != 0);
    else            g = (gm[i] != 0);

    unsigned long long inc;
    if (g) {
        inc = 1ull;                                  // ground field
    } else {
        // on-the-fly grad_pos / grad_neg from depth row stencil
        int r = n / WW; int j = n - r*WW;
        const float* drow = depth + (size_t)b*NP + (size_t)r*WW;
        int c1 = max(j-2, 0), c2 = min(j+2, WW-1);
        float diff1 = drow[min(c1+1, WW-1)] - drow[max(c1-1, 0)];
        float diff2 = drow[min(c2+1, WW-1)] - drow[max(c2-1, 0)];
        float rml1 = fmaxf(diff1, 0.f), rml2 = fmaxf(diff2, 0.f);
        float lmr1 = fmaxf(-diff1, 0.f), lmr2 = fmaxf(-diff2, 0.f);
        float rmldd = fmaxf(rml1 - rml2, 0.f);
        float lmrdd = fmaxf(lmr2 - lmr1, 0.f);
        float gp = (j < WW/2) ? rmldd : lmrdd;
        float gn = (j < WW/2) ? lmrdd : rmldd;
        inc = 0ull;
        if (gp > 0.f)    inc += (1ull << 36) + ((gp > 0.01f) ? (1ull << 48) : 0ull);
        if (gn > 0.f)    inc += (1ull << 12) + ((gn > 0.01f) ? (1ull << 24) : 0ull);
    }
    if (inc) atomicAdd(&g_packed[cell], inc);
}

// fused odds + 3x3 maxpool: tile 32x8 with 1-cell halo of neg-odds in smem
__global__ void __launch_bounds__(256) oddspool_kernel(float* __restrict__ out) {
    __shared__ float sneg[10][34];
    int b  = blockIdx.z;
    int tx0 = blockIdx.x*32, tz0 = blockIdx.y*8;
    const unsigned long long* pk = &g_packed[(size_t)b*GG];
    int tid = threadIdx.y*32 + threadIdx.x;

    float PMIN = logf(0.1f) - log1pf(-0.1f);
    float PMAX = logf(0.9f) - log1pf(-0.9f);

    for (int idx = tid; idx < 340; idx += 256) {
        int lz = idx / 34, lx = idx - lz*34;
        int gz = tz0 + lz - 1, gx = tx0 + lx - 1;
        float no = 0.f;
        if (gz >= 0 && gz < SS && gx >= 0 && gx < SS) {
            unsigned long long v = pk[gz*SS + gx];
            int gc  = (int)( v        & 0xFFFull);
            int nn_ = (int)((v >> 12) & 0xFFFull);
            int occn= (int)((v >> 24) & 0xFFFull);
            int np_ = (int)((v >> 36) & 0xFFFull);
            bool freen = (gc > 0) && (nn_ == 0);
            bool unkn  = (!freen) && (nn_ < 3);
            if (!(freen || unkn)) {
                float pr = (float)occn / (float)nn_;
                no = logf(pr) - log1pf(-pr);
            }
            bool freep = (gc > 0) && (np_ == 0);
            bool unkp  = (!freep) && (np_ < 3);
            if (freep || unkp) no = 0.f;
            no = fminf(fmaxf(no, 0.f), PMAX);
        }
        sneg[lz][lx] = no;
    }
    __syncthreads();

    int gx = tx0 + threadIdx.x, gz = tz0 + threadIdx.y;
    unsigned long long v = pk[gz*SS + gx];
    int gc  = (int)( v        & 0xFFFull);
    int np_ = (int)((v >> 36) & 0xFFFull);
    int occp= (int)( v >> 48);
    bool freep = (gc > 0) && (np_ == 0);
    bool unkp  = (!freep) && (np_ < 3);
    float po;
    if (freep)      po = logf(1e-10f) - log1pf(-1e-10f);
    else if (unkp)  po = 0.f;
    else { float pr = (float)occp / (float)np_; po = logf(pr) - log1pf(-pr); }
    po = fminf(fmaxf(po, PMIN), PMAX);

    float m = sneg[threadIdx.y][threadIdx.x];
    #pragma unroll
    for (int dz = 0; dz < 3; dz++)
        #pragma unroll
        for (int dx = 0; dx < 3; dx++)
            m = fmaxf(m, sneg[threadIdx.y + dz][threadIdx.x + dx]);

    out[(size_t)b*GG + gz*SS + gx] = po - m;
}

// ---------------- launcher ----------------
extern "C" void kernel_launch(void* const* d_in, const int* in_sizes, int n_in,
                              void* d_out, int out_size) {
    const float*         depth = (const float*)d_in[0];
    const float*         ptc   = (const float*)d_in[1];
    const unsigned char* gm    = (const unsigned char*)d_in[2];
    float*               out   = (float*)d_out;

    const int TPB = 256;
    const int PT_BLKS   = (TOTAL_PTS   + TPB - 1) / TPB;     // 61440
    const int CELL_BLKS = (TOTAL_CELLS + TPB - 1) / TPB;     // 8192

    zero_kernel<<<CELL_BLKS, TPB>>>();
    detect_kernel<<<32, TPB>>>(gm);
    hist_kernel<<<BB*HBLKS_PER_B, TPB>>>(ptc);               // 480 blocks
    scan_kernel<<<BB, 256>>>();
    cand_kernel<<<TOTAL_PTS/4/TPB, TPB>>>(ptc);              // 15360 blocks
    thr_kernel<<<BB, 256>>>();
    scatter_kernel<<<PT_BLKS, TPB>>>(ptc, depth, gm);
    oddspool_kernel<<<dim3(SS/32, SS/8, BB), dim3(32, 8)>>>(out);
}

// round 3
// speedup vs baseline: 2.1464x; 1.1971x over previous
#include <cuda_runtime.h>
#include <cstdint>

#define BB 32
#define HH 384
#define WW 1280
#define NP (HH*WW)            // 491520
#define SS 256
#define GG (SS*SS)
#define NB 4096
#define CAP 8192
#define TOTAL_PTS (BB*NP)     // 15,728,640
#define TOTAL_CELLS (BB*GG)   // 2,097,152

#define YMINF (-16.0f)
#define BIN_SCALE (4096.0f/288.0f)

#define PTS_PER_HBLK 32768
#define HBLKS_PER_B (NP/PTS_PER_HBLK)   // 15

// ---------------- device scratch ----------------
// packed per-cell counters, 12-bit fields:
//   [48:60) occp | [36:48) normp | [24:36) occn | [12:24) normn | [0:12) ground
__device__ unsigned long long g_packed[TOTAL_CELLS];
__device__ unsigned int       g_hist[BB*NB];
__device__ unsigned char      g_code[TOTAL_PTS];
__device__ float              g_cand[BB*CAP];
__device__ int                g_candcnt[BB];
__device__ float              g_thr[BB];
__device__ int                g_sel[BB*3];
__device__ int                g_is_int32;

__device__ __forceinline__ int y_to_bin(float y) {
    int bin = (int)__fmul_rn(__fsub_rn(y, YMINF), BIN_SCALE);
    return min(max(bin, 0), NB-1);
}

// ---------------- kernels ----------------
__global__ void zero_kernel() {
    int i = blockIdx.x*blockDim.x + threadIdx.x;
    if (i < TOTAL_CELLS) g_packed[i] = 0ull;
    if (i < BB*NB) g_hist[i] = 0u;
    if (i < BB) g_candcnt[i] = 0;
    if (i == 0) g_is_int32 = 1;
}

// detect ground_mask dtype: random 0/1 bytes read as int32 are almost never in {0,1}
__global__ void detect_kernel(const unsigned char* __restrict__ gm) {
    int i = blockIdx.x*blockDim.x + threadIdx.x;
    const int* gi = (const int*)gm;
    int v = gi[i];
    if (v != 0 && v != 1) g_is_int32 = 0;
}

// coalesced row-stencil: 4-bit grad code per pixel
__global__ void __launch_bounds__(256) grad_kernel(const float* __restrict__ depth) {
    __shared__ float sd[WW];
    int row = blockIdx.x;                    // 0 .. BB*HH-1
    const float* d = depth + (size_t)row*WW;
    for (int i = threadIdx.x; i < WW/4; i += 256)
        ((float4*)sd)[i] = ((const float4*)d)[i];
    __syncthreads();
    unsigned char* crow = g_code + (size_t)row*WW;
    for (int j = threadIdx.x; j < WW; j += 256) {
        int c1 = max(j-2, 0), c2 = min(j+2, WW-1);
        float diff1 = sd[min(c1+1, WW-1)] - sd[max(c1-1, 0)];
        float diff2 = sd[min(c2+1, WW-1)] - sd[max(c2-1, 0)];
        float rml1 = fmaxf(diff1, 0.f), rml2 = fmaxf(diff2, 0.f);
        float lmr1 = fmaxf(-diff1, 0.f), lmr2 = fmaxf(-diff2, 0.f);
        float rmldd = fmaxf(rml1 - rml2, 0.f);
        float lmrdd = fmaxf(lmr2 - lmr1, 0.f);
        float gp = (j < WW/2) ? rmldd : lmrdd;
        float gn = (j < WW/2) ? lmrdd : rmldd;
        unsigned int c = (gp > 0.f) | ((gp > 0.01f) << 1)
                       | ((gn > 0.f) << 2) | ((gn > 0.01f) << 3);
        crow[j] = (unsigned char)c;
    }
}

// privatized shared-memory histogram; one block = 32768 y's of one batch
__global__ void __launch_bounds__(256) hist_kernel(const float* __restrict__ ptc) {
    __shared__ unsigned int sh[NB];
    int b   = blockIdx.x / HBLKS_PER_B;
    int blk = blockIdx.x % HBLKS_PER_B;
    for (int i = threadIdx.x; i < NB; i += 256) sh[i] = 0u;
    __syncthreads();
    const float4* yp = (const float4*)(ptc + (size_t)b*(3*NP) + NP
                                       + (size_t)blk*PTS_PER_HBLK);
    #pragma unroll 4
    for (int i = threadIdx.x; i < PTS_PER_HBLK/4; i += 256) {
        float4 v = yp[i];
        atomicAdd(&sh[y_to_bin(v.x)], 1u);
        atomicAdd(&sh[y_to_bin(v.y)], 1u);
        atomicAdd(&sh[y_to_bin(v.z)], 1u);
        atomicAdd(&sh[y_to_bin(v.w)], 1u);
    }
    __syncthreads();
    unsigned int* gh = &g_hist[(size_t)b*NB];
    for (int i = threadIdx.x; i < NB; i += 256) {
        unsigned int s = sh[i];
        if (s) atomicAdd(&gh[i], s);
    }
}

__global__ void scan_kernel() {
    int b = blockIdx.x, t = threadIdx.x;
    int lane = t & 31, w = t >> 5;
    const unsigned int* h = &g_hist[(size_t)b*NB];
    const int PER = NB/256;          // 16
    int base = t*PER;
    unsigned int s = 0;
    #pragma unroll
    for (int i = 0; i < PER/4; i++) {
        uint4 v = ((const uint4*)(h + base))[i];
        s += v.x + v.y + v.z + v.w;
    }
    // block exclusive scan of s
    unsigned int v = s;
    #pragma unroll
    for (int o = 1; o < 32; o <<= 1) {
        unsigned int u = __shfl_up_sync(0xFFFFFFFFu, v, o);
        if (lane >= o) v += u;
    }
    __shared__ unsigned int wsum[8];
    if (lane == 31) wsum[w] = v;
    __syncthreads();
    if (t < 8) {
        unsigned int x = wsum[t];
        #pragma unroll
        for (int o = 1; o < 8; o <<= 1) {
            unsigned int u = __shfl_up_sync(0xFFu, x, o);
            if (t >= o) x += u;
        }
        wsum[t] = x;
    }
    __syncthreads();
    unsigned int cum = v - s + (w ? wsum[w-1] : 0u);

    float idxf = __fmul_rn(0.7f, (float)(NP-1));
    unsigned int k = (unsigned int)floorf(idxf);
    for (int i = 0; i < PER; i++) {
        unsigned int c = h[base+i];
        if (k   >= cum && k   < cum + c) { g_sel[b*3+0] = base+i; g_sel[b*3+2] = (int)cum; }
        if (k+1 >= cum && k+1 < cum + c) { g_sel[b*3+1] = base+i; }
        cum += c;
    }
}

__global__ void __launch_bounds__(256) cand_kernel(const float* __restrict__ ptc) {
    int i = blockIdx.x*blockDim.x + threadIdx.x;        // over TOTAL_PTS/4
    int b = i / (NP/4); int n4 = i - b*(NP/4);
    const float4* yp = (const float4*)(ptc + (size_t)b*(3*NP) + NP);
    float4 v = yp[n4];
    int lo = g_sel[b*3+0], hi = g_sel[b*3+1];
    float ys[4] = {v.x, v.y, v.z, v.w};
    #pragma unroll
    for (int q = 0; q < 4; q++) {
        int bin = y_to_bin(ys[q]);
        if (bin >= lo && bin <= hi) {
            int pos = atomicAdd(&g_candcnt[b], 1);
            if (pos < CAP) g_cand[b*CAP + pos] = ys[q];
        }
    }
}

__global__ void thr_kernel() {
    int b = blockIdx.x, t = threadIdx.x;
    int n = g_candcnt[b]; if (n > CAP) n = CAP;
    int cb = g_sel[b*3+2];
    float idxf = __fmul_rn(0.7f, (float)(NP-1));
    float lowf = floorf(idxf);
    float hw = __fsub_rn(idxf, lowf);
    float lw = __fsub_rn(1.0f, hw);
    int rk = (int)lowf - cb;
    __shared__ float sk, sk1;
    if (t == 0) { sk = 0.f; sk1 = 0.f; }
    __syncthreads();
    for (int c = t; c < n; c += blockDim.x) {
        float v = g_cand[b*CAP + c];
        int r = 0;
        for (int j = 0; j < n; j++) {
            float u = g_cand[b*CAP + j];
            r += (u < v) || (u == v && j < c);
        }
        if (r == rk)     sk  = v;
        if (r == rk + 1) sk1 = v;
    }
    __syncthreads();
    if (t == 0)
        g_thr[b] = __fadd_rn(__fmul_rn(sk, lw), __fmul_rn(sk1, hw));
}

// vectorized scatter: 4 points per thread, code-table lookup, one 64-bit RED per point
__global__ void __launch_bounds__(256) scatter_kernel(
    const float* __restrict__ ptc,
    const unsigned char* __restrict__ gm)
{
    int i = blockIdx.x*blockDim.x + threadIdx.x;      // < TOTAL_PTS/4
    int b = i / (NP/4); int n4 = i - b*(NP/4);
    const float* p = ptc + (size_t)b*(3*NP);
    float4 x4 = ((const float4*)p)[n4];
    float4 y4 = ((const float4*)(p + NP))[n4];
    float4 z4 = ((const float4*)(p + 2*NP))[n4];
    uchar4 cd = ((const uchar4*)g_code)[(size_t)b*(NP/4) + n4];
    float thr = g_thr[b];

    unsigned int gbits;
    if (g_is_int32) {
        int4 g = ((const int4*)gm)[(size_t)b*(NP/4) + n4];
        gbits = (g.x != 0) | ((g.y != 0) << 1) | ((g.z != 0) << 2) | ((g.w != 0) << 3);
    } else {
        uchar4 g = ((const uchar4*)gm)[(size_t)b*(NP/4) + n4];
        gbits = (g.x != 0) | ((g.y != 0) << 1) | ((g.z != 0) << 2) | ((g.w != 0) << 3);
    }

    float xs[4] = {x4.x, x4.y, x4.z, x4.w};
    float ys[4] = {y4.x, y4.y, y4.z, y4.w};
    float zs[4] = {z4.x, z4.y, z4.z, z4.w};
    unsigned char cs[4] = {cd.x, cd.y, cd.z, cd.w};

    #pragma unroll
    for (int q = 0; q < 4; q++) {
        float x = xs[q], z = zs[q];
        if (!(x >= 0.0f && x <= (float)(SS-1) && z >= 0.0f && z <= (float)(SS-1))) continue;
        if (!(ys[q] < thr)) continue;
        int xi = min(max((int)x, 0), SS-1);
        int zi = min(max((int)z, 0), SS-1);
        int cell = b*GG + zi*SS + xi;
        unsigned long long inc;
        if ((gbits >> q) & 1u) {
            inc = 1ull;                              // ground
        } else {
            unsigned int c = cs[q];
            inc = 0ull;
            if (c & 1u) inc += (1ull << 36) + ((c & 2u) ? (1ull << 48) : 0ull);
            if (c & 4u) inc += (1ull << 12) + ((c & 8u) ? (1ull << 24) : 0ull);
            if (!inc) continue;
        }
        atomicAdd(&g_packed[cell], inc);
    }
}

// fused odds + 3x3 maxpool
__global__ void __launch_bounds__(256) oddspool_kernel(float* __restrict__ out) {
    __shared__ float sneg[10][34];
    int b  = blockIdx.z;
    int tx0 = blockIdx.x*32, tz0 = blockIdx.y*8;
    const unsigned long long* pk = &g_packed[(size_t)b*GG];
    int tid = threadIdx.y*32 + threadIdx.x;

    float PMIN = logf(0.1f) - log1pf(-0.1f);
    float PMAX = logf(0.9f) - log1pf(-0.9f);

    for (int idx = tid; idx < 340; idx += 256) {
        int lz = idx / 34, lx = idx - lz*34;
        int gz = tz0 + lz - 1, gx = tx0 + lx - 1;
        float no = 0.f;
        if (gz >= 0 && gz < SS && gx >= 0 && gx < SS) {
            unsigned long long v = pk[gz*SS + gx];
            int gc  = (int)( v        & 0xFFFull);
            int nn_ = (int)((v >> 12) & 0xFFFull);
            int occn= (int)((v >> 24) & 0xFFFull);
            int np_ = (int)((v >> 36) & 0xFFFull);
            bool freen = (gc > 0) && (nn_ == 0);
            bool unkn  = (!freen) && (nn_ < 3);
            if (!(freen || unkn)) {
                float pr = (float)occn / (float)nn_;
                no = logf(pr) - log1pf(-pr);
            }
            bool freep = (gc > 0) && (np_ == 0);
            bool unkp  = (!freep) && (np_ < 3);
            if (freep || unkp) no = 0.f;
            no = fminf(fmaxf(no, 0.f), PMAX);
        }
        sneg[lz][lx] = no;
    }
    __syncthreads();

    int gx = tx0 + threadIdx.x, gz = tz0 + threadIdx.y;
    unsigned long long v = pk[gz*SS + gx];
    int gc  = (int)( v        & 0xFFFull);
    int np_ = (int)((v >> 36) & 0xFFFull);
    int occp= (int)( v >> 48);
    bool freep = (gc > 0) && (np_ == 0);
    bool unkp  = (!freep) && (np_ < 3);
    float po;
    if (freep)      po = logf(1e-10f) - log1pf(-1e-10f);
    else if (unkp)  po = 0.f;
    else { float pr = (float)occp / (float)np_; po = logf(pr) - log1pf(-pr); }
    po = fminf(fmaxf(po, PMIN), PMAX);

    float m = sneg[threadIdx.y][threadIdx.x];
    #pragma unroll
    for (int dz = 0; dz < 3; dz++)
        #pragma unroll
        for (int dx = 0; dx < 3; dx++)
            m = fmaxf(m, sneg[threadIdx.y + dz][threadIdx.x + dx]);

    out[(size_t)b*GG + gz*SS + gx] = po - m;
}

// ---------------- launcher ----------------
extern "C" void kernel_launch(void* const* d_in, const int* in_sizes, int n_in,
                              void* d_out, int out_size) {
    const float*         depth = (const float*)d_in[0];
    const float*         ptc   = (const float*)d_in[1];
    const unsigned char* gm    = (const unsigned char*)d_in[2];
    float*               out   = (float*)d_out;

    const int TPB = 256;
    const int CELL_BLKS = (TOTAL_CELLS + TPB - 1) / TPB;     // 8192

    zero_kernel<<<CELL_BLKS, TPB>>>();
    detect_kernel<<<32, TPB>>>(gm);
    grad_kernel<<<BB*HH, TPB>>>(depth);                      // 12288 blocks
    hist_kernel<<<BB*HBLKS_PER_B, TPB>>>(ptc);               // 480 blocks
    scan_kernel<<<BB, 256>>>();
    cand_kernel<<<TOTAL_PTS/4/TPB, TPB>>>(ptc);              // 15360 blocks
    thr_kernel<<<BB, 256>>>();
    scatter_kernel<<<TOTAL_PTS/4/TPB, TPB>>>(ptc, gm);       // 15360 blocks
    oddspool_kernel<<<dim3(SS/32, SS/8, BB), dim3(32, 8)>>>(out);
}